// round 1
// baseline (speedup 1.0000x reference)
#include <cuda_runtime.h>
#include <cstdint>

#define T_SEQ 2048
#define BATCH 256
#define HID   64
#define INP   7

typedef unsigned long long ull;

__device__ __forceinline__ ull fma2(ull a, ull b, ull c) {
    ull d;
    asm("fma.rn.f32x2 %0, %1, %2, %3;" : "=l"(d) : "l"(a), "l"(b), "l"(c));
    return d;
}
__device__ __forceinline__ ull add2(ull a, ull b) {
    ull d;
    asm("add.rn.f32x2 %0, %1, %2;" : "=l"(d) : "l"(a), "l"(b));
    return d;
}
__device__ __forceinline__ ull pack2(float lo, float hi) {
    ull d; asm("mov.b64 %0, {%1, %2};" : "=l"(d) : "f"(lo), "f"(hi)); return d;
}
__device__ __forceinline__ float2 unpack2(ull a) {
    float2 r; asm("mov.b64 {%0, %1}, %2;" : "=f"(r.x), "=f"(r.y) : "l"(a)); return r;
}
__device__ __forceinline__ float fsig(float x) {
    float e = __expf(-x);
    return __fdividef(1.0f, 1.0f + e);
}
__device__ __forceinline__ float ftanh_(float x) {
    float e = __expf(2.0f * x);
    return 1.0f - __fdividef(2.0f, e + 1.0f);
}

// One CTA = one batch chain. Thread g in [0,256) owns gate g (i/f/g/o x 64 units).
// Recurrent weights (64 floats/thread) live in registers as 32 f32x2 pairs.
// Per step: z_g = W_hh[g]·h + W_ih[g]·x_t + bias_g (packed f32x2 FMAs),
// then 64 "updater" threads compute gates -> c,h. Two barriers per step.
// Epilogue: backward LSTM = ONE step on x[T-1] from zero state (scan[0] of the
// reversed sequence is the last element after re-reversal), then the tiny linear.
__global__ void __launch_bounds__(256, 2)
bilstm_kernel(const float* __restrict__ x,      // [B,T,I]
              const float* __restrict__ Wih_f,  // [256,7]
              const float* __restrict__ Whh_f,  // [256,64]
              const float* __restrict__ bih_f,  // [256]
              const float* __restrict__ bhh_f,  // [256]
              const float* __restrict__ Wih_b,  // [256,7]
              const float* __restrict__ Whh_b,  // [256,64] (unused: h0=0 for the single bwd step)
              const float* __restrict__ bih_b,  // [256]
              const float* __restrict__ bhh_b,  // [256]
              const float* __restrict__ Wlin,   // [3,128]
              const float* __restrict__ blin,   // [3]
              float* __restrict__ out)          // [B,3]
{
    __shared__ __align__(16) float sh_h[128];   // [0:64) fwd h, [64:128) bwd h at epilogue
    __shared__ float sh_z[256];
    __shared__ __align__(16) float sh_x[8];     // current x_t (7 + zero pad)

    const int tid = threadIdx.x;
    const int b  = blockIdx.x;
    const float* xb = x + (size_t)b * T_SEQ * INP;

    // ---- one-time weight load into registers ----
    ull wrec[32];
    const ull* wrow = reinterpret_cast<const ull*>(Whh_f + tid * HID);  // row g, 256B-aligned
#pragma unroll
    for (int m = 0; m < 32; m++) wrec[m] = wrow[m];

    float wih_s[8];
#pragma unroll
    for (int i = 0; i < INP; i++) wih_s[i] = Wih_f[tid * INP + i];
    wih_s[7] = 0.0f;
    ull wih2[4];
#pragma unroll
    for (int m = 0; m < 4; m++) wih2[m] = pack2(wih_s[2 * m], wih_s[2 * m + 1]);

    const float bias = bih_f[tid] + bhh_f[tid];

    if (tid < 128) sh_h[tid] = 0.0f;
    if (tid < INP) sh_x[tid] = xb[tid];
    if (tid == 7)  sh_x[7] = 0.0f;
    float c = 0.0f;
    __syncthreads();

    for (int t = 0; t < T_SEQ; t++) {
        // prefetch x[t+1] early so LDG latency hides under the FMA block
        float xpre = 0.0f;
        if (tid < INP && t + 1 < T_SEQ) xpre = __ldg(xb + (size_t)(t + 1) * INP + tid);

        // z_g = W_hh[g] · h  (+ W_ih[g] · x_t), packed f32x2
        ull acc0 = 0ull, acc1 = 0ull, acc2 = 0ull, acc3 = 0ull;
        const ulonglong2* h2 = reinterpret_cast<const ulonglong2*>(sh_h);
#pragma unroll
        for (int m = 0; m < 8; m++) {
            ulonglong2 ha = h2[2 * m];
            ulonglong2 hbv = h2[2 * m + 1];
            acc0 = fma2(wrec[4 * m + 0], ha.x,  acc0);
            acc1 = fma2(wrec[4 * m + 1], ha.y,  acc1);
            acc2 = fma2(wrec[4 * m + 2], hbv.x, acc2);
            acc3 = fma2(wrec[4 * m + 3], hbv.y, acc3);
        }
        const ulonglong2* x2 = reinterpret_cast<const ulonglong2*>(sh_x);
        {
            ulonglong2 xv = x2[0];
            ulonglong2 xw = x2[1];
            acc0 = fma2(wih2[0], xv.x, acc0);
            acc1 = fma2(wih2[1], xv.y, acc1);
            acc2 = fma2(wih2[2], xw.x, acc2);
            acc3 = fma2(wih2[3], xw.y, acc3);
        }
        ull s = add2(add2(acc0, acc1), add2(acc2, acc3));
        float2 sf = unpack2(s);
        sh_z[tid] = sf.x + sf.y + bias;
        __syncthreads();

        // gate nonlinearities + state update (PyTorch gate order i,f,g,o)
        if (tid < HID) {
            float zi = sh_z[tid];
            float zf = sh_z[tid + 64];
            float zg = sh_z[tid + 128];
            float zo = sh_z[tid + 192];
            float ig = fsig(zi);
            float fg = fsig(zf);
            float gg = ftanh_(zg);
            float og = fsig(zo);
            c = fg * c + ig * gg;
            sh_h[tid] = og * ftanh_(c);
        }
        if (tid < INP && t + 1 < T_SEQ) sh_x[tid] = xpre;
        __syncthreads();
    }

    // ---- epilogue: backward direction = ONE step on x[T-1] from zero state ----
    // (sh_x still holds x[T-1]; W_hh_bwd @ 0 == 0 so it never enters)
    {
        float zb = bih_b[tid] + bhh_b[tid];
#pragma unroll
        for (int i = 0; i < INP; i++) zb += Wih_b[tid * INP + i] * sh_x[i];
        sh_z[tid] = zb;
        __syncthreads();
        if (tid < HID) {
            float ig = fsig(sh_z[tid]);
            float gg = ftanh_(sh_z[tid + 128]);
            float og = fsig(sh_z[tid + 192]);
            float cb = ig * gg;              // f*c0 = 0
            sh_h[64 + tid] = og * ftanh_(cb);
        }
        __syncthreads();
    }

    // ---- final linear: out[b] = W_lin @ concat(h_f, h_b) + b_lin ----
    if (tid < 3) {
        float a = blin[tid];
#pragma unroll 16
        for (int k = 0; k < 128; k++) a += Wlin[tid * 128 + k] * sh_h[k];
        out[b * 3 + tid] = a;
    }
}

extern "C" void kernel_launch(void* const* d_in, const int* in_sizes, int n_in,
                              void* d_out, int out_size) {
    (void)in_sizes; (void)n_in; (void)out_size;
    bilstm_kernel<<<BATCH, 256>>>(
        (const float*)d_in[0],  (const float*)d_in[1], (const float*)d_in[2],
        (const float*)d_in[3],  (const float*)d_in[4], (const float*)d_in[5],
        (const float*)d_in[6],  (const float*)d_in[7], (const float*)d_in[8],
        (const float*)d_in[9],  (const float*)d_in[10], (float*)d_out);
}